// round 12
// baseline (speedup 1.0000x reference)
#include <cuda_runtime.h>
#include <math.h>
#include <stdint.h>

// Problem dims (fixed by the dataset)
#define NN 1000
#define PP 50000
#define ZZ 20
#define LL 10

// Persistent grid for the sequential CAVI kernel
#define NC 148                 // CTAs == SM count; all co-resident
#define NT 352                 // threads per CTA (11 warps)
#define NWARP (NT / 32)        // 11
#define CH 338                 // columns per CTA: 148*338 = 50024 >= 50000

// GEMM config
#define NCH 8                  // n-chunks for ZtX GEMM
#define NCHN (NN / NCH)        // 125

// Scratch (static device globals; no allocation)
__device__ float g_ZtX[ZZ * PP];                 // 4 MB
__device__ float g_ZtXp[NCH * ZZ * PP];          // 32 MB partials
// Publish slots: {m, tag, S, tag} per CTA, double-buffered by step parity.
// 16B store carries data+tag together -> no fences, no atomics.
__device__ uint4 g_pub[2][NC];

// ---------------------------------------------------------------------------
// Reset publish tags (runs first in the graph each launch)
// ---------------------------------------------------------------------------
__global__ void reset_kernel() {
    int i = threadIdx.x;
    if (i < 2 * NC) ((uint4*)g_pub)[i] = make_uint4(0u, 0u, 0u, 0u);
}

// ---------------------------------------------------------------------------
// ZtX GEMM: partials over n-chunks, then reduce.
// ---------------------------------------------------------------------------
__global__ __launch_bounds__(256) void ztx_partial_kernel(
    const float* __restrict__ data, const float* __restrict__ mz) {
    __shared__ float sz[NCHN * ZZ];  // 125*20 floats = 10 KB
    int c = blockIdx.y;
    for (int t = threadIdx.x; t < NCHN * ZZ; t += blockDim.x)
        sz[t] = mz[c * (NCHN * ZZ) + t];
    __syncthreads();

    int g = blockIdx.x * blockDim.x + threadIdx.x;
    if (g >= PP / 4) return;
    int j = g * 4;

    float4 acc[ZZ];
#pragma unroll
    for (int k = 0; k < ZZ; k++) acc[k] = make_float4(0.f, 0.f, 0.f, 0.f);

    const float* dp = data + (size_t)c * NCHN * PP + j;
    for (int nn = 0; nn < NCHN; nn++) {
        float4 d = *(const float4*)(dp + (size_t)nn * PP);
#pragma unroll
        for (int k = 0; k < ZZ; k++) {
            float zv = sz[nn * ZZ + k];
            acc[k].x += d.x * zv;
            acc[k].y += d.y * zv;
            acc[k].z += d.z * zv;
            acc[k].w += d.w * zv;
        }
    }
#pragma unroll
    for (int k = 0; k < ZZ; k++)
        *(float4*)&g_ZtXp[(size_t)c * (ZZ * PP) + k * PP + j] = acc[k];
}

__global__ void ztx_reduce_kernel() {
    int idx = blockIdx.x * blockDim.x + threadIdx.x;
    if (idx >= ZZ * PP) return;
    float s = 0.f;
#pragma unroll
    for (int c = 0; c < NCH; c++) s += g_ZtXp[c * (ZZ * PP) + idx];
    g_ZtX[idx] = s;
}

// ---------------------------------------------------------------------------
// Reduction / publish helpers
// ---------------------------------------------------------------------------
// Order-preserving bijection f32 -> u32 (total order incl. -INF), so the
// warp max can use the integer redux unit (redux.f32 is rejected by ptxas
// on this target; redux.u32 is sm_80+).
__device__ __forceinline__ unsigned f2ord(float x) {
    unsigned u = __float_as_uint(x);
    return (u & 0x80000000u) ? ~u : (u | 0x80000000u);
}
__device__ __forceinline__ float ord2f(unsigned u) {
    return __uint_as_float((u & 0x80000000u) ? (u ^ 0x80000000u) : ~u);
}
__device__ __forceinline__ float warp_max(float v) {
    unsigned r;
    asm volatile("redux.sync.max.u32 %0, %1, 0xffffffff;"
                 : "=r"(r) : "r"(f2ord(v)));
    return ord2f(r);
}
__device__ __forceinline__ float warp_sum(float v) {
#pragma unroll
    for (int o = 16; o; o >>= 1) v += __shfl_xor_sync(0xffffffffu, v, o);
    return v;
}
__device__ __forceinline__ void pub_store(uint4* p, float m, float S, unsigned tag) {
    asm volatile("st.volatile.global.v4.u32 [%0], {%1,%2,%3,%4};"
                 :: "l"(p), "r"(__float_as_uint(m)), "r"(tag),
                    "r"(__float_as_uint(S)), "r"(tag) : "memory");
}
__device__ __forceinline__ uint4 pub_load(const uint4* p) {
    uint4 v;
    asm volatile("ld.volatile.global.v4.u32 {%0,%1,%2,%3}, [%4];"
                 : "=r"(v.x), "=r"(v.y), "=r"(v.z), "=r"(v.w) : "l"(p));
    return v;
}

// ---------------------------------------------------------------------------
// CAVI kernel: persistent grid, 1 column per thread, all state in registers.
// Per (k,l) step: CTA softmax partial (m, S); tag-fused 16B publish; all
// warp0s poll the 148 slots (tag == step) and combine -> fence/atomic-free
// grid barrier merged with the reduction itself.
// ---------------------------------------------------------------------------
__global__ void __launch_bounds__(NT, 1)
cavi_kernel(const float* __restrict__ mzz, const float* __restrict__ mw_in,
            const float* __restrict__ a_in, const float* __restrict__ tau_p,
            const float* __restrict__ tau0, const float* __restrict__ pi,
            float* __restrict__ out_mw, float* __restrict__ out_vw,
            float* __restrict__ out_a) {
    __shared__ float sWm[NWARP];
    __shared__ float sWs[NWARP];
    __shared__ float2 sMT;

    const int tid = threadIdx.x;
    const int w = tid >> 5;
    const int lane = tid & 31;
    const int cta = blockIdx.x;
    const int col = cta * CH + tid;
    const bool active = (tid < CH) && (col < PP);
    const float tau = __ldg(tau_p);

    // W[j] = sum_l mw[l,j,col]*a[l,j,col] for own column (registers)
    float W[ZZ];
#pragma unroll
    for (int j = 0; j < ZZ; j++) W[j] = 0.f;
    if (active) {
#pragma unroll
        for (int j = 0; j < ZZ; j++) {
            float s = 0.f;
#pragma unroll
            for (int l = 0; l < LL; l++)
                s += __ldg(&mw_in[((size_t)l * ZZ + j) * PP + col]) *
                     __ldg(&a_in[((size_t)l * ZZ + j) * PP + col]);
            W[j] = s;
        }
    }

    int b = 0;  // global step index (0..199)
    for (int k = 0; k < ZZ; k++) {
        const float Ez = __ldg(&mzz[k * ZZ + k]);
        const float invEz = 1.f / Ez;

        // Prologue (register-only): RtZk, D, log pi for own column
        float RtZk = 0.f, D = 0.f, lp = 0.f;
        if (active) {
            float acc = g_ZtX[(size_t)k * PP + col];
            float wkv = 0.f;
#pragma unroll
            for (int j = 0; j < ZZ; j++) {
                float mj = __ldg(&mzz[k * ZZ + j]);
                if (j == k) wkv = W[j];
                else acc -= mj * W[j];
            }
            RtZk = acc;
            D = acc - Ez * wkv;
            lp = __logf(__ldg(&pi[(size_t)k * PP + col]));
        }

        const float s2 = 1.f / (Ez * tau);
        const float l_s2 = __logf(s2);

        const size_t lst = (size_t)ZZ * PP;
        const float* pmw = mw_in + (size_t)k * PP + col;
        const float* pa = a_in + (size_t)k * PP + col;
        float mw_nxt = 0.f, a_nxt = 0.f;
        if (active) { mw_nxt = __ldg(pmw); a_nxt = __ldg(pa); }

        for (int l = 0; l < LL; l++, b++) {
            const float t0 = __ldg(&tau0[l * ZZ + k]);
            const float s0inv = 1.f / t0;
            const float s2p = s2 + s0inv;
            const float c0 = 0.5f * (l_s2 - __logf(s2p));
            const float c1 = 0.5f * (s0inv / s2p) * (tau * invEz);
            const float varn = 1.f / (tau * Ez + t0);
            const float tv = tau * varn;

            const float mwv = mw_nxt, av = a_nxt;
            if (l + 1 < LL && active) {  // prefetch next l (hides DRAM latency)
                mw_nxt = __ldg(pmw + (size_t)(l + 1) * lst);
                a_nxt = __ldg(pa + (size_t)(l + 1) * lst);
            }

            float E = 0.f, s = -INFINITY;
            if (active) {
                E = fmaf(Ez, mwv * av, D);
                s = fmaf(c1 * E, E, lp + c0);
            }

            // warp-local flash partial: m_w (int redux), e, S_w (shfl sum)
            float m_w = warp_max(s);
            float e = active ? __expf(s - m_w) : 0.f;
            float S_w = warp_sum(e);
            if (!lane) { sWm[w] = m_w; sWs[w] = S_w; }

            // mean output is softmax-independent: store now, off critical path
            float mn = 0.f;
            if (active) {
                mn = tv * E;
                out_mw[(size_t)(l * ZZ + k) * PP + col] = mn;
            }
            __syncthreads();  // bar1

            if (w == 0) {
                // CTA partial (m_r, S_r) from the 11 warp partials
                float mj = (lane < NWARP) ? sWm[lane] : -INFINITY;
                float Sj = (lane < NWARP) ? sWs[lane] : 0.f;
                float m_r = warp_max(mj);
                float t = (lane < NWARP && Sj > 0.f) ? Sj * __expf(mj - m_r) : 0.f;
                t = warp_sum(t);

                const unsigned tag = (unsigned)(b + 1);
                uint4* buf = g_pub[b & 1];
                if (!lane) pub_store(&buf[cta], m_r, t, tag);

                // poll all 148 slots until every tag == b+1 (5 per lane)
                float2 part[5];
                bool ok;
                do {
                    ok = true;
#pragma unroll
                    for (int it = 0; it < 5; it++) {
                        int j = lane + it * 32;
                        if (j < NC) {
                            uint4 v = pub_load(&buf[j]);
                            ok &= (v.y == tag) & (v.w == tag);
                            part[it] = make_float2(__uint_as_float(v.x),
                                                   __uint_as_float(v.z));
                        } else {
                            part[it] = make_float2(-INFINITY, 0.f);
                        }
                    }
                } while (!__all_sync(0xffffffffu, ok));

                // combine the 148 partials
                float M = -INFINITY;
#pragma unroll
                for (int it = 0; it < 5; it++) M = fmaxf(M, part[it].x);
                M = warp_max(M);
                float T = 0.f;
#pragma unroll
                for (int it = 0; it < 5; it++)
                    if (part[it].y > 0.f) T += part[it].y * __expf(part[it].x - M);
                T = warp_sum(T);
                if (!lane) sMT = make_float2(M, T);
            }
            __syncthreads();  // bar2

            const float M = sMT.x, T = sMT.y;
            // scale uniform per warp; all lanes compute (no broadcast shfl)
            const float sc = __expf(m_w - M) / T;

            if (active) {
                float an = e * sc;
                out_a[(size_t)(l * ZZ + k) * PP + col] = an;
                D = fmaf(-Ez, mn * an, E);  // D_new = E - Ez*mean*alpha
            }
            if (cta == 0 && tid == 0) out_vw[l * ZZ + k] = varn;
        }

        // epilogue: W[k] = (RtZk - D)/Ez (register select, no dynamic index)
        if (active) {
            float wkf = (RtZk - D) * invEz;
#pragma unroll
            for (int j = 0; j < ZZ; j++)
                if (j == k) W[j] = wkf;
        }
    }
}

// ---------------------------------------------------------------------------
// Launch
// ---------------------------------------------------------------------------
extern "C" void kernel_launch(void* const* d_in, const int* in_sizes, int n_in,
                              void* d_out, int out_size) {
    const float* data = (const float*)d_in[0];
    const float* mz = (const float*)d_in[1];
    const float* mzz = (const float*)d_in[2];
    const float* mw = (const float*)d_in[3];
    // d_in[4] = var_w (unused: fully overwritten)
    const float* alpha = (const float*)d_in[5];
    const float* tau = (const float*)d_in[6];
    const float* tau0 = (const float*)d_in[7];
    const float* pi = (const float*)d_in[8];

    float* out = (float*)d_out;
    float* out_mw = out;                              // [L,Z,P]
    float* out_vw = out + (size_t)LL * ZZ * PP;       // [L,Z]
    float* out_a = out_vw + LL * ZZ;                  // [L,Z,P]

    reset_kernel<<<1, 2 * NC>>>();

    dim3 g2((PP / 4 + 255) / 256, NCH);
    ztx_partial_kernel<<<g2, 256>>>(data, mz);
    ztx_reduce_kernel<<<(ZZ * PP + 255) / 256, 256>>>();

    cavi_kernel<<<NC, NT>>>(mzz, mw, alpha, tau, tau0, pi,
                            out_mw, out_vw, out_a);
}

// round 13
// speedup vs baseline: 1.0778x; 1.0778x over previous
#include <cuda_runtime.h>
#include <math.h>
#include <stdint.h>

// Problem dims (fixed by the dataset)
#define NN 1000
#define PP 50000
#define ZZ 20
#define LL 10

// Persistent grid for the sequential CAVI kernel
#define NC 74                  // CTAs (1 per SM, all co-resident)
#define NT 704                 // threads per CTA (22 warps)
#define NWARP (NT / 32)        // 22
#define CH 676                 // columns per CTA: 74*676 = 50024 >= 50000
#define NSLOT 3                // ceil(NC/32) poll iterations per lane

// GEMM config
#define NCH 8                  // n-chunks for ZtX GEMM
#define NCHN (NN / NCH)        // 125

// Scratch (static device globals; no allocation)
__device__ float g_ZtX[ZZ * PP];                 // 4 MB
__device__ float g_ZtXp[NCH * ZZ * PP];          // 32 MB partials
// Publish slots: {m, tag, S, tag} per CTA, double-buffered by step parity.
// Single 16B relaxed.gpu store carries data+tag -> no fences, no atomics.
__device__ uint4 g_pub[2][NC];

// ---------------------------------------------------------------------------
// Reset publish tags (runs first in the graph each launch)
// ---------------------------------------------------------------------------
__global__ void reset_kernel() {
    int i = threadIdx.x;
    if (i < 2 * NC) ((uint4*)g_pub)[i] = make_uint4(0u, 0u, 0u, 0u);
}

// ---------------------------------------------------------------------------
// ZtX GEMM: partials over n-chunks, then reduce.
// ---------------------------------------------------------------------------
__global__ __launch_bounds__(256) void ztx_partial_kernel(
    const float* __restrict__ data, const float* __restrict__ mz) {
    __shared__ float sz[NCHN * ZZ];  // 125*20 floats
    int c = blockIdx.y;
    for (int t = threadIdx.x; t < NCHN * ZZ; t += blockDim.x)
        sz[t] = mz[c * (NCHN * ZZ) + t];
    __syncthreads();

    int g = blockIdx.x * blockDim.x + threadIdx.x;
    if (g >= PP / 4) return;
    int j = g * 4;

    float4 acc[ZZ];
#pragma unroll
    for (int k = 0; k < ZZ; k++) acc[k] = make_float4(0.f, 0.f, 0.f, 0.f);

    const float* dp = data + (size_t)c * NCHN * PP + j;
    for (int nn = 0; nn < NCHN; nn++) {
        float4 d = *(const float4*)(dp + (size_t)nn * PP);
#pragma unroll
        for (int k = 0; k < ZZ; k++) {
            float zv = sz[nn * ZZ + k];
            acc[k].x += d.x * zv;
            acc[k].y += d.y * zv;
            acc[k].z += d.z * zv;
            acc[k].w += d.w * zv;
        }
    }
#pragma unroll
    for (int k = 0; k < ZZ; k++)
        *(float4*)&g_ZtXp[(size_t)c * (ZZ * PP) + k * PP + j] = acc[k];
}

__global__ void ztx_reduce_kernel() {
    int idx = blockIdx.x * blockDim.x + threadIdx.x;
    if (idx >= ZZ * PP) return;
    float s = 0.f;
#pragma unroll
    for (int c = 0; c < NCH; c++) s += g_ZtXp[c * (ZZ * PP) + idx];
    g_ZtX[idx] = s;
}

// ---------------------------------------------------------------------------
// Reduction / publish helpers
// ---------------------------------------------------------------------------
// Order-preserving bijection f32 -> u32 so warp max can use integer redux
// (redux.f32 rejected by ptxas on sm_103; redux.u32 is sm_80+).
__device__ __forceinline__ unsigned f2ord(float x) {
    unsigned u = __float_as_uint(x);
    return (u & 0x80000000u) ? ~u : (u | 0x80000000u);
}
__device__ __forceinline__ float ord2f(unsigned u) {
    return __uint_as_float((u & 0x80000000u) ? (u ^ 0x80000000u) : ~u);
}
__device__ __forceinline__ float warp_max(float v) {
    unsigned r;
    asm volatile("redux.sync.max.u32 %0, %1, 0xffffffff;"
                 : "=r"(r) : "r"(f2ord(v)));
    return ord2f(r);
}
__device__ __forceinline__ float warp_sum(float v) {
#pragma unroll
    for (int o = 16; o; o >>= 1) v += __shfl_xor_sync(0xffffffffu, v, o);
    return v;
}
// GPU-scope relaxed 128-bit publish/poll (NOT volatile: volatile carries
// system-scope strength and was the R12 regression).
__device__ __forceinline__ void pub_store(uint4* p, float m, float S, unsigned tag) {
    asm volatile("st.relaxed.gpu.global.v4.u32 [%0], {%1,%2,%3,%4};"
                 :: "l"(p), "r"(__float_as_uint(m)), "r"(tag),
                    "r"(__float_as_uint(S)), "r"(tag) : "memory");
}
__device__ __forceinline__ uint4 pub_load(const uint4* p) {
    uint4 v;
    asm volatile("ld.relaxed.gpu.global.v4.u32 {%0,%1,%2,%3}, [%4];"
                 : "=r"(v.x), "=r"(v.y), "=r"(v.z), "=r"(v.w) : "l"(p) : "memory");
    return v;
}

// ---------------------------------------------------------------------------
// CAVI kernel: persistent 74-CTA grid, 1 column per thread. W lives in SMEM
// (frees registers for NT=704). Per (k,l) step: CTA softmax partial (m, S);
// tag-fused relaxed.gpu 16B publish; warp0 polls the 74 slots and combines.
// ---------------------------------------------------------------------------
#define SMEM_FLOATS (ZZ * CH + ZZ * ZZ + 2 * NWARP + 2)
#define SMEM_BYTES (SMEM_FLOATS * 4)

__global__ void __launch_bounds__(NT, 1)
cavi_kernel(const float* __restrict__ mzz, const float* __restrict__ mw_in,
            const float* __restrict__ a_in, const float* __restrict__ tau_p,
            const float* __restrict__ tau0, const float* __restrict__ pi,
            float* __restrict__ out_mw, float* __restrict__ out_vw,
            float* __restrict__ out_a) {
    extern __shared__ float sm[];
    float* sW = sm;                        // [ZZ][CH] collapsed loadings
    float* sMzz = sm + ZZ * CH;            // [ZZ*ZZ]
    float* sWm = sMzz + ZZ * ZZ;           // [NWARP]
    float* sWs = sWm + NWARP;              // [NWARP]
    float2* sMT = (float2*)(sWs + NWARP);  // combined (M, T)

    const int tid = threadIdx.x;
    const int w = tid >> 5;
    const int lane = tid & 31;
    const int cta = blockIdx.x;
    const int col = cta * CH + tid;
    const bool active = (tid < CH) && (col < PP);
    const float tau = __ldg(tau_p);

    // stage mzz in SMEM
    for (int i = tid; i < ZZ * ZZ; i += NT) sMzz[i] = __ldg(&mzz[i]);

    // W[j][tid] = sum_l mw[l,j,col]*a[l,j,col]
    if (active) {
#pragma unroll
        for (int j = 0; j < ZZ; j++) {
            float s = 0.f;
#pragma unroll
            for (int l = 0; l < LL; l++)
                s += __ldg(&mw_in[((size_t)l * ZZ + j) * PP + col]) *
                     __ldg(&a_in[((size_t)l * ZZ + j) * PP + col]);
            sW[j * CH + tid] = s;
        }
    }
    __syncthreads();

    // prefetched k-state (k=0) and (k=0,l=0) inputs
    float ztx_nxt = 0.f, pi_nxt = 1.f, mw_nxt = 0.f, a_nxt = 0.f;
    if (active) {
        ztx_nxt = __ldg(&g_ZtX[col]);
        pi_nxt = __ldg(&pi[col]);
        mw_nxt = __ldg(&mw_in[col]);
        a_nxt = __ldg(&a_in[col]);
    }

    int b = 0;  // global step index (0..199)
    for (int k = 0; k < ZZ; k++) {
        const float Ez = sMzz[k * ZZ + k];
        const float invEz = 1.f / Ez;

        // Prologue: D = ZtX[k] - mzz[k,:] @ W[:,col]; RtZk = D + Ez*Wk
        float RtZk = 0.f, D = 0.f, lp = 0.f;
        if (active) {
            float dot = 0.f;
#pragma unroll
            for (int j = 0; j < ZZ; j++)
                dot = fmaf(sMzz[k * ZZ + j], sW[j * CH + tid], dot);
            D = ztx_nxt - dot;
            RtZk = fmaf(Ez, sW[k * CH + tid], D);
            lp = __logf(pi_nxt);
        }

        const float s2 = 1.f / (Ez * tau);
        const float l_s2 = __logf(s2);

        for (int l = 0; l < LL; l++, b++) {
            const float t0 = __ldg(&tau0[l * ZZ + k]);
            const float s0inv = 1.f / t0;
            const float s2p = s2 + s0inv;
            const float c0 = 0.5f * (l_s2 - __logf(s2p));
            const float c1 = 0.5f * (s0inv / s2p) * (tau * invEz);
            const float varn = 1.f / (tau * Ez + t0);
            const float tv = tau * varn;

            const float mwv = mw_nxt, av = a_nxt;
            // prefetch next (l,k) inputs; at l==0 also next-k ZtX/pi
            {
                int nl = (l + 1 < LL) ? l + 1 : 0;
                int nk = (l + 1 < LL) ? k : k + 1;
                if (nk < ZZ && active) {
                    size_t off = ((size_t)nl * ZZ + nk) * PP + col;
                    mw_nxt = __ldg(&mw_in[off]);
                    a_nxt = __ldg(&a_in[off]);
                }
                if (l == 0 && k + 1 < ZZ && active) {
                    ztx_nxt = __ldg(&g_ZtX[(size_t)(k + 1) * PP + col]);
                    pi_nxt = __ldg(&pi[(size_t)(k + 1) * PP + col]);
                }
            }

            float E = 0.f, s = -INFINITY;
            if (active) {
                E = fmaf(Ez, mwv * av, D);
                s = fmaf(c1 * E, E, lp + c0);
            }

            // warp-local flash partial: m_w (int redux), e, S_w (shfl sum)
            float m_w = warp_max(s);
            float e = active ? __expf(s - m_w) : 0.f;
            float S_w = warp_sum(e);
            if (!lane) { sWm[w] = m_w; sWs[w] = S_w; }

            // mean output is softmax-independent: store now, off critical path
            float mn = 0.f;
            if (active) {
                mn = tv * E;
                out_mw[(size_t)(l * ZZ + k) * PP + col] = mn;
            }
            __syncthreads();  // bar1

            if (w == 0) {
                // CTA partial (m_r, S_r) from the 22 warp partials
                float mj = (lane < NWARP) ? sWm[lane] : -INFINITY;
                float Sj = (lane < NWARP) ? sWs[lane] : 0.f;
                float m_r = warp_max(mj);
                float t = (lane < NWARP && Sj > 0.f) ? Sj * __expf(mj - m_r) : 0.f;
                t = warp_sum(t);

                const unsigned tag = (unsigned)(b + 1);
                uint4* buf = g_pub[b & 1];
                if (!lane) pub_store(&buf[cta], m_r, t, tag);

                // poll all 74 slots until every tag == b+1 (3 per lane)
                float2 part[NSLOT];
                bool ok;
                do {
                    ok = true;
#pragma unroll
                    for (int it = 0; it < NSLOT; it++) {
                        int j = lane + it * 32;
                        if (j < NC) {
                            uint4 v = pub_load(&buf[j]);
                            ok &= (v.y == tag) & (v.w == tag);
                            part[it] = make_float2(__uint_as_float(v.x),
                                                   __uint_as_float(v.z));
                        } else {
                            part[it] = make_float2(-INFINITY, 0.f);
                        }
                    }
                } while (!__all_sync(0xffffffffu, ok));

                // combine the 74 partials
                float M = -INFINITY;
#pragma unroll
                for (int it = 0; it < NSLOT; it++) M = fmaxf(M, part[it].x);
                M = warp_max(M);
                float T = 0.f;
#pragma unroll
                for (int it = 0; it < NSLOT; it++)
                    if (part[it].y > 0.f) T += part[it].y * __expf(part[it].x - M);
                T = warp_sum(T);
                if (!lane) *sMT = make_float2(M, T);
            }
            __syncthreads();  // bar2

            const float M = sMT->x, T = sMT->y;
            // scale uniform per warp; all lanes compute (no broadcast shfl)
            const float sc = __expf(m_w - M) / T;

            if (active) {
                float an = e * sc;
                out_a[(size_t)(l * ZZ + k) * PP + col] = an;
                D = fmaf(-Ez, mn * an, E);  // D_new = E - Ez*mean*alpha
            }
            if (cta == 0 && tid == 0) out_vw[l * ZZ + k] = varn;
        }

        // epilogue: W[k][col] = (RtZk - D)/Ez (own column; same thread reads
        // it next prologue, ordered by the step barriers)
        if (active) sW[k * CH + tid] = (RtZk - D) * invEz;
    }
}

// ---------------------------------------------------------------------------
// Launch
// ---------------------------------------------------------------------------
extern "C" void kernel_launch(void* const* d_in, const int* in_sizes, int n_in,
                              void* d_out, int out_size) {
    const float* data = (const float*)d_in[0];
    const float* mz = (const float*)d_in[1];
    const float* mzz = (const float*)d_in[2];
    const float* mw = (const float*)d_in[3];
    // d_in[4] = var_w (unused: fully overwritten)
    const float* alpha = (const float*)d_in[5];
    const float* tau = (const float*)d_in[6];
    const float* tau0 = (const float*)d_in[7];
    const float* pi = (const float*)d_in[8];

    float* out = (float*)d_out;
    float* out_mw = out;                              // [L,Z,P]
    float* out_vw = out + (size_t)LL * ZZ * PP;       // [L,Z]
    float* out_a = out_vw + LL * ZZ;                  // [L,Z,P]

    reset_kernel<<<1, 2 * NC>>>();

    dim3 g2((PP / 4 + 255) / 256, NCH);
    ztx_partial_kernel<<<g2, 256>>>(data, mz);
    ztx_reduce_kernel<<<(ZZ * PP + 255) / 256, 256>>>();

    cudaFuncSetAttribute(cavi_kernel, cudaFuncAttributeMaxDynamicSharedMemorySize,
                         SMEM_BYTES);
    cavi_kernel<<<NC, NT, SMEM_BYTES>>>(mzz, mw, alpha, tau, tau0, pi,
                                        out_mw, out_vw, out_a);
}

// round 16
// speedup vs baseline: 1.3809x; 1.2813x over previous
#include <cuda_runtime.h>
#include <math.h>
#include <stdint.h>

// Problem dims (fixed by the dataset)
#define NN 1000
#define PP 50000
#define ZZ 20
#define LL 10

// Persistent one-warp-per-CTA grid for the sequential CAVI kernel
#define NC 143                 // CTAs (1 warp each, all co-resident on 148 SMs)
#define NT 32                  // ONE warp per CTA: no block barriers at all
#define NCOL 11                // columns per lane
#define CHW (NCOL * NT)        // 352 columns per CTA; 143*352 = 50336 >= 50000
#define NSLOT 5                // ceil(NC/32) poll slots per lane

// GEMM config
#define NCH 8                  // n-chunks for ZtX GEMM
#define NCHN (NN / NCH)        // 125

// Scratch (static device globals; no allocation)
__device__ float g_W[ZZ * PP];                   // 4 MB collapsed loadings
__device__ float g_ZtX[ZZ * PP];                 // 4 MB
__device__ float g_ZtXp[NCH * ZZ * PP];          // 32 MB partials
// Publish slots: {m, tag, S, tag} per CTA, double-buffered by step parity.
// Each 8B half is self-validating (tag rides along) -> no fences, no atomics.
__device__ uint4 g_pub[2][NC];

// ---------------------------------------------------------------------------
// Reset publish tags (runs first in the graph each launch)
// ---------------------------------------------------------------------------
__global__ void reset_kernel() {
    int i = blockIdx.x * blockDim.x + threadIdx.x;
    if (i < 2 * NC) ((uint4*)g_pub)[i] = make_uint4(0u, 0u, 0u, 0u);
}

// ---------------------------------------------------------------------------
// winit: g_W[j,i] = sum_l mean_w[l,j,i] * alpha[l,j,i]
// ---------------------------------------------------------------------------
__global__ void winit_kernel(const float* __restrict__ mw,
                             const float* __restrict__ al) {
    int idx = blockIdx.x * blockDim.x + threadIdx.x;
    if (idx >= ZZ * PP) return;
    float s = 0.f;
#pragma unroll
    for (int l = 0; l < LL; l++)
        s += mw[l * (ZZ * PP) + idx] * al[l * (ZZ * PP) + idx];
    g_W[idx] = s;
}

// ---------------------------------------------------------------------------
// ZtX GEMM: partials over n-chunks, then reduce.
// ---------------------------------------------------------------------------
__global__ __launch_bounds__(256) void ztx_partial_kernel(
    const float* __restrict__ data, const float* __restrict__ mz) {
    __shared__ float sz[NCHN * ZZ];  // 125*20 floats
    int c = blockIdx.y;
    for (int t = threadIdx.x; t < NCHN * ZZ; t += blockDim.x)
        sz[t] = mz[c * (NCHN * ZZ) + t];
    __syncthreads();

    int g = blockIdx.x * blockDim.x + threadIdx.x;
    if (g >= PP / 4) return;
    int j = g * 4;

    float4 acc[ZZ];
#pragma unroll
    for (int k = 0; k < ZZ; k++) acc[k] = make_float4(0.f, 0.f, 0.f, 0.f);

    const float* dp = data + (size_t)c * NCHN * PP + j;
    for (int nn = 0; nn < NCHN; nn++) {
        float4 d = *(const float4*)(dp + (size_t)nn * PP);
#pragma unroll
        for (int k = 0; k < ZZ; k++) {
            float zv = sz[nn * ZZ + k];
            acc[k].x += d.x * zv;
            acc[k].y += d.y * zv;
            acc[k].z += d.z * zv;
            acc[k].w += d.w * zv;
        }
    }
#pragma unroll
    for (int k = 0; k < ZZ; k++)
        *(float4*)&g_ZtXp[(size_t)c * (ZZ * PP) + k * PP + j] = acc[k];
}

__global__ void ztx_reduce_kernel() {
    int idx = blockIdx.x * blockDim.x + threadIdx.x;
    if (idx >= ZZ * PP) return;
    float s = 0.f;
#pragma unroll
    for (int c = 0; c < NCH; c++) s += g_ZtXp[c * (ZZ * PP) + idx];
    g_ZtX[idx] = s;
}

// ---------------------------------------------------------------------------
// Reduction / publish helpers
// ---------------------------------------------------------------------------
// Order-preserving bijection f32 -> u32 so warp max can use integer redux
// (redux.f32 rejected by ptxas on sm_103; redux.u32 is sm_80+).
__device__ __forceinline__ unsigned f2ord(float x) {
    unsigned u = __float_as_uint(x);
    return (u & 0x80000000u) ? ~u : (u | 0x80000000u);
}
__device__ __forceinline__ float ord2f(unsigned u) {
    return __uint_as_float((u & 0x80000000u) ? (u ^ 0x80000000u) : ~u);
}
__device__ __forceinline__ float warp_max(float v) {
    unsigned r;
    asm volatile("redux.sync.max.u32 %0, %1, 0xffffffff;"
                 : "=r"(r) : "r"(f2ord(v)));
    return ord2f(r);
}
__device__ __forceinline__ float warp_sum(float v) {
#pragma unroll
    for (int o = 16; o; o >>= 1) v += __shfl_xor_sync(0xffffffffu, v, o);
    return v;
}
// GPU-scope relaxed 128-bit publish/poll (volatile = SYS strength = slow).
__device__ __forceinline__ void pub_store(uint4* p, float m, float S, unsigned tag) {
    asm volatile("st.relaxed.gpu.global.v4.u32 [%0], {%1,%2,%3,%4};"
                 :: "l"(p), "r"(__float_as_uint(m)), "r"(tag),
                    "r"(__float_as_uint(S)), "r"(tag) : "memory");
}
__device__ __forceinline__ uint4 pub_load(const uint4* p) {
    uint4 v;
    asm volatile("ld.relaxed.gpu.global.v4.u32 {%0,%1,%2,%3}, [%4];"
                 : "=r"(v.x), "=r"(v.y), "=r"(v.z), "=r"(v.w) : "l"(p) : "memory");
    return v;
}

// ---------------------------------------------------------------------------
// CAVI kernel: 143 one-warp CTAs, 11 columns per lane, per-step state in
// registers, W in per-CTA SMEM (touched only at k-prologue/epilogue).
// Per (k,l) step: register-tree + redux/shfl partial; tag-fused 16B publish;
// the warp polls the 143 slots and combines. NO block barriers anywhere.
// ---------------------------------------------------------------------------
__global__ void __launch_bounds__(NT, 1)
cavi_kernel(const float* __restrict__ mzz, const float* __restrict__ mw_in,
            const float* __restrict__ a_in, const float* __restrict__ tau_p,
            const float* __restrict__ tau0, const float* __restrict__ pi,
            float* __restrict__ out_mw, float* __restrict__ out_vw,
            float* __restrict__ out_a) {
    __shared__ float sW[ZZ][CHW];     // 28 KB collapsed loadings
    __shared__ float sMzz[ZZ * ZZ];

    const int lane = threadIdx.x;
    const int cta = blockIdx.x;
    const int base = cta * CHW;
    const float tau = __ldg(tau_p);

    for (int t = lane; t < ZZ * ZZ; t += NT) sMzz[t] = __ldg(&mzz[t]);

    bool act[NCOL];
#pragma unroll
    for (int i = 0; i < NCOL; i++) act[i] = (base + i * NT + lane) < PP;

    // Load W rows into SMEM (coalesced per i)
#pragma unroll
    for (int j = 0; j < ZZ; j++)
#pragma unroll
        for (int i = 0; i < NCOL; i++)
            sW[j][i * NT + lane] =
                act[i] ? __ldg(&g_W[(size_t)j * PP + base + i * NT + lane]) : 0.f;
    __syncwarp();  // sMzz is cross-lane

    // prefetched k-state (k=0) and (k=0,l=0) inputs
    float ztx_nxt[NCOL], pi_nxt[NCOL], mwn[NCOL], aln[NCOL];
#pragma unroll
    for (int i = 0; i < NCOL; i++) {
        int col = base + i * NT + lane;
        ztx_nxt[i] = act[i] ? __ldg(&g_ZtX[col]) : 0.f;
        pi_nxt[i] = act[i] ? __ldg(&pi[col]) : 1.f;
        mwn[i] = act[i] ? __ldg(&mw_in[col]) : 0.f;
        aln[i] = act[i] ? __ldg(&a_in[col]) : 0.f;
    }

    int b = 0;  // global step index (0..199)
    for (int k = 0; k < ZZ; k++) {
        const float Ez = sMzz[k * ZZ + k];
        const float invEz = 1.f / Ez;

        // Prologue: D = ZtX[k] - mzz[k,:] @ W; RtZk = D + Ez*Wk; lp = log(pi)
        float D[NCOL], RtZk[NCOL], lp[NCOL];
#pragma unroll
        for (int i = 0; i < NCOL; i++) {
            float dot = 0.f;
#pragma unroll
            for (int j = 0; j < ZZ; j++)
                dot = fmaf(sMzz[k * ZZ + j], sW[j][i * NT + lane], dot);
            D[i] = ztx_nxt[i] - dot;
            RtZk[i] = fmaf(Ez, sW[k][i * NT + lane], D[i]);
            lp[i] = __logf(pi_nxt[i]);
        }

        const float s2 = 1.f / (Ez * tau);
        const float l_s2 = __logf(s2);

        for (int l = 0; l < LL; l++, b++) {
            const float t0 = __ldg(&tau0[l * ZZ + k]);
            const float s0inv = 1.f / t0;
            const float s2p = s2 + s0inv;
            const float c0 = 0.5f * (l_s2 - __logf(s2p));
            const float c1 = 0.5f * (s0inv / s2p) * (tau * invEz);
            const float varn = 1.f / (tau * Ez + t0);
            const float tv = tau * varn;

            // E, s, local max over 11 cols (register tree)
            float E[NCOL], sv[NCOL];
            float mloc = -INFINITY;
#pragma unroll
            for (int i = 0; i < NCOL; i++) {
                if (act[i]) {
                    E[i] = fmaf(Ez, mwn[i] * aln[i], D[i]);
                    sv[i] = fmaf(c1 * E[i], E[i], lp[i] + c0);
                    mloc = fmaxf(mloc, sv[i]);
                } else {
                    E[i] = 0.f;
                    sv[i] = -INFINITY;
                }
            }
            float m_r = warp_max(mloc);

            float ev[NCOL];
            float ssum = 0.f;
#pragma unroll
            for (int i = 0; i < NCOL; i++) {
                ev[i] = act[i] ? __expf(sv[i] - m_r) : 0.f;
                ssum += ev[i];
            }
            float S_r = warp_sum(ssum);

            // publish CTA partial immediately (critical path head)
            const unsigned tag = (unsigned)(b + 1);
            uint4* buf = g_pub[b & 1];
            if (lane == 0) pub_store(&buf[cta], m_r, S_r, tag);

            // softmax-independent work while the publish/poll latency runs:
            // mean output stores + next-step prefetch
#pragma unroll
            for (int i = 0; i < NCOL; i++)
                if (act[i])
                    out_mw[(size_t)(l * ZZ + k) * PP + base + i * NT + lane] =
                        tv * E[i];
            {
                int nl = (l + 1 < LL) ? l + 1 : 0;
                int nk = (l + 1 < LL) ? k : k + 1;
                if (nk < ZZ) {
#pragma unroll
                    for (int i = 0; i < NCOL; i++)
                        if (act[i]) {
                            size_t off =
                                ((size_t)nl * ZZ + nk) * PP + base + i * NT + lane;
                            mwn[i] = __ldg(&mw_in[off]);
                            aln[i] = __ldg(&a_in[off]);
                        }
                }
                if (l == 0 && k + 1 < ZZ) {
#pragma unroll
                    for (int i = 0; i < NCOL; i++)
                        if (act[i]) {
                            size_t col = (size_t)(k + 1) * PP + base + i * NT + lane;
                            ztx_nxt[i] = __ldg(&g_ZtX[col]);
                            pi_nxt[i] = __ldg(&pi[col]);
                        }
                }
            }
            if (cta == 0 && lane == 0) out_vw[l * ZZ + k] = varn;

            // poll all 143 slots until every tag == b+1 (5 per lane);
            // nanosleep backoff after a failed sweep cuts spin L2 traffic
            float2 part[NSLOT];
            bool ok;
            do {
                ok = true;
#pragma unroll
                for (int it = 0; it < NSLOT; it++) {
                    int j = lane + it * 32;
                    if (j < NC) {
                        uint4 v = pub_load(&buf[j]);
                        ok &= (v.y == tag) & (v.w == tag);
                        part[it] = make_float2(__uint_as_float(v.x),
                                               __uint_as_float(v.z));
                    } else {
                        part[it] = make_float2(-INFINITY, 0.f);
                    }
                }
                if (!__all_sync(0xffffffffu, ok)) {
                    __nanosleep(32);
                    ok = false;
                }
            } while (!ok);

            // combine the 143 partials (whole warp)
            float M = -INFINITY;
#pragma unroll
            for (int it = 0; it < NSLOT; it++) M = fmaxf(M, part[it].x);
            M = warp_max(M);
            float T = 0.f;
#pragma unroll
            for (int it = 0; it < NSLOT; it++)
                if (part[it].y > 0.f) T += part[it].y * __expf(part[it].x - M);
            T = warp_sum(T);

            const float sc = __expf(m_r - M) / T;

            // alpha out + D update
#pragma unroll
            for (int i = 0; i < NCOL; i++)
                if (act[i]) {
                    float an = ev[i] * sc;
                    out_a[(size_t)(l * ZZ + k) * PP + base + i * NT + lane] = an;
                    D[i] = fmaf(-Ez, (tv * E[i]) * an, E[i]);
                }
        }

        // epilogue: W[k] = (RtZk - D)/Ez (own columns; same lanes re-read)
#pragma unroll
        for (int i = 0; i < NCOL; i++)
            if (act[i]) sW[k][i * NT + lane] = (RtZk[i] - D[i]) * invEz;
    }
}

// ---------------------------------------------------------------------------
// Launch
// ---------------------------------------------------------------------------
extern "C" void kernel_launch(void* const* d_in, const int* in_sizes, int n_in,
                              void* d_out, int out_size) {
    const float* data = (const float*)d_in[0];
    const float* mz = (const float*)d_in[1];
    const float* mzz = (const float*)d_in[2];
    const float* mw = (const float*)d_in[3];
    // d_in[4] = var_w (unused: fully overwritten)
    const float* alpha = (const float*)d_in[5];
    const float* tau = (const float*)d_in[6];
    const float* tau0 = (const float*)d_in[7];
    const float* pi = (const float*)d_in[8];

    float* out = (float*)d_out;
    float* out_mw = out;                              // [L,Z,P]
    float* out_vw = out + (size_t)LL * ZZ * PP;       // [L,Z]
    float* out_a = out_vw + LL * ZZ;                  // [L,Z,P]

    reset_kernel<<<1, 512>>>();
    winit_kernel<<<(ZZ * PP + 255) / 256, 256>>>(mw, alpha);

    dim3 g2((PP / 4 + 255) / 256, NCH);
    ztx_partial_kernel<<<g2, 256>>>(data, mz);
    ztx_reduce_kernel<<<(ZZ * PP + 255) / 256, 256>>>();

    cavi_kernel<<<NC, NT>>>(mzz, mw, alpha, tau, tau0, pi,
                            out_mw, out_vw, out_a);
}